// round 2
// baseline (speedup 1.0000x reference)
#include <cuda_runtime.h>
#include <cuda_bf16.h>
#include <cstdint>
#include <cstdio>

// ---------------------------------------------------------------------------
// AtomAttentionPairBias: B=1, Nq=Nk=4096, C=128, H=4, c=32, CZ=16  (all fp32)
//
// Plan:
//   1. ln_kernel (x2): LN(a) and LN(s)*sscale per row.
//   2. dual_gemm<ADALN> (x2): aq = sigmoid(sn@Wg+bg)*LN(a) + sn@Wb
//   3. dual_gemm<QG>: q = (aq@Wq+bq)*scale ; g = sigmoid(aq@Wgate)
//   4. dual_gemm<KV>: k = ak@Wk ; v = ak@Wv
//   5. attn_kernel: flash attention, z-bias fused (z streamed ONCE),
//      QK^T and PV via tf32 mma.sync; epilogue applies gate g -> og
//   6. dual_gemm<FINAL>: out = sigmoid(s_q@Ws+bs) * (og@Wo)
// ---------------------------------------------------------------------------

#define NSEQ 4096
#define CDIM 128
#define NHEAD 4
#define HDIM 32
#define CZ 16
#define EPS 1e-5f
#define QK_SCALE 0.17677669529663687f   // 1/sqrt(32)

// scratch: 11 slices of [4096 x 128] fp32
__device__ float g_scratch[11u * NSEQ * CDIM];

__constant__ float c_wb[CZ * NHEAD];  // Wbias (row-major [cz][h])
__constant__ float c_lnz[CZ];         // lnz_scale

__device__ __forceinline__ float sigmoidf_(float x) { return 1.f / (1.f + __expf(-x)); }

// ------------------------------ LN kernel ---------------------------------
__global__ void ln_kernel(const float* __restrict__ a, const float* __restrict__ s,
                          const float* __restrict__ sscale,
                          float* __restrict__ lnA, float* __restrict__ sn) {
    int warp = threadIdx.x >> 5, lane = threadIdx.x & 31;
    int row = blockIdx.x * 8 + warp;
    if (row >= NSEQ) return;
    const float4* ap = (const float4*)(a + (size_t)row * CDIM);
    const float4* sp = (const float4*)(s + (size_t)row * CDIM);
    float4 av = ap[lane];
    float4 sv = sp[lane];

    float s1 = av.x + av.y + av.z + av.w;
    float s2 = av.x*av.x + av.y*av.y + av.z*av.z + av.w*av.w;
    float t1 = sv.x + sv.y + sv.z + sv.w;
    float t2 = sv.x*sv.x + sv.y*sv.y + sv.z*sv.z + sv.w*sv.w;
    #pragma unroll
    for (int o = 16; o > 0; o >>= 1) {
        s1 += __shfl_xor_sync(~0u, s1, o);
        s2 += __shfl_xor_sync(~0u, s2, o);
        t1 += __shfl_xor_sync(~0u, t1, o);
        t2 += __shfl_xor_sync(~0u, t2, o);
    }
    float ma = s1 * (1.f/CDIM);
    float ra = rsqrtf(s2 * (1.f/CDIM) - ma*ma + EPS);
    float ms = t1 * (1.f/CDIM);
    float rs = rsqrtf(t2 * (1.f/CDIM) - ms*ms + EPS);

    float4 sc = ((const float4*)sscale)[lane];
    float4 oa, os;
    oa.x = (av.x - ma) * ra; oa.y = (av.y - ma) * ra;
    oa.z = (av.z - ma) * ra; oa.w = (av.w - ma) * ra;
    os.x = (sv.x - ms) * rs * sc.x; os.y = (sv.y - ms) * rs * sc.y;
    os.z = (sv.z - ms) * rs * sc.z; os.w = (sv.w - ms) * rs * sc.w;
    ((float4*)(lnA + (size_t)row * CDIM))[lane] = oa;
    ((float4*)(sn  + (size_t)row * CDIM))[lane] = os;
}

// --------------------------- dual GEMM kernel ------------------------------
// acc1 = X1@W1 , acc2 = X2@W2 over [32 rows x 128 cols] per block.
#define MODE_ADALN 0
#define MODE_QG    1
#define MODE_KV    2
#define MODE_FINAL 3

template<int MODE>
__global__ __launch_bounds__(256) void dual_gemm(
    const float* __restrict__ X1, const float* __restrict__ X2,
    const float* __restrict__ W1, const float* __restrict__ W2,
    const float* __restrict__ b1, const float* __restrict__ b2,
    const float* __restrict__ E,
    float* __restrict__ out1, float* __restrict__ out2) {

    __shared__ float sX1[32][16];
    __shared__ float sX2[32][16];
    __shared__ float sW1[16][128];
    __shared__ float sW2[16][128];

    int tid = threadIdx.x;
    int row0 = blockIdx.x * 32;
    int ty = tid >> 4;   // 0..15 -> rows {ty, ty+16}
    int tx = tid & 15;   // 0..15 -> cols {tx + 16*j}

    float acc1[2][8], acc2[2][8];
    #pragma unroll
    for (int i = 0; i < 2; i++)
        #pragma unroll
        for (int j = 0; j < 8; j++) { acc1[i][j] = 0.f; acc2[i][j] = 0.f; }

    for (int kc = 0; kc < CDIM; kc += 16) {
        #pragma unroll
        for (int i = 0; i < 2; i++) {
            int e = tid + i * 256;
            int r = e >> 4, kk = e & 15;
            sX1[r][kk] = X1[(size_t)(row0 + r) * CDIM + kc + kk];
            sX2[r][kk] = X2[(size_t)(row0 + r) * CDIM + kc + kk];
        }
        #pragma unroll
        for (int i = 0; i < 8; i++) {
            int e = tid + i * 256;
            int kk = e >> 7, c = e & 127;
            sW1[kk][c] = W1[(size_t)(kc + kk) * CDIM + c];
            sW2[kk][c] = W2[(size_t)(kc + kk) * CDIM + c];
        }
        __syncthreads();
        #pragma unroll
        for (int kk = 0; kk < 16; kk++) {
            float x1a = sX1[ty][kk],      x1b = sX1[ty + 16][kk];
            float x2a = sX2[ty][kk],      x2b = sX2[ty + 16][kk];
            #pragma unroll
            for (int j = 0; j < 8; j++) {
                float w1 = sW1[kk][tx + 16 * j];
                float w2 = sW2[kk][tx + 16 * j];
                acc1[0][j] += x1a * w1; acc1[1][j] += x1b * w1;
                acc2[0][j] += x2a * w2; acc2[1][j] += x2b * w2;
            }
        }
        __syncthreads();
    }

    #pragma unroll
    for (int i = 0; i < 2; i++) {
        int r = row0 + ty + i * 16;
        #pragma unroll
        for (int j = 0; j < 8; j++) {
            int cc = tx + 16 * j;
            size_t idx = (size_t)r * CDIM + cc;
            if (MODE == MODE_ADALN) {
                float gsig = sigmoidf_(acc1[i][j] + b1[cc]);
                out1[idx] = gsig * E[idx] + acc2[i][j];
            } else if (MODE == MODE_QG) {
                out1[idx] = (acc1[i][j] + b1[cc]) * QK_SCALE;
                out2[idx] = sigmoidf_(acc2[i][j]);
            } else if (MODE == MODE_KV) {
                out1[idx] = acc1[i][j];
                out2[idx] = acc2[i][j];
            } else { // FINAL
                out1[idx] = sigmoidf_(acc2[i][j] + b2[cc]) * acc1[i][j];
            }
        }
    }
}

// --------------------------- attention kernel ------------------------------
#define K_STRIDE 132
#define V_STRIDE 136
#define P_STRIDE 68
#define SMEM_FLOATS (64 * K_STRIDE + 64 * V_STRIDE + NHEAD * 32 * P_STRIDE)
#define SMEM_BYTES  (SMEM_FLOATS * 4)

__device__ __forceinline__ uint32_t f2tf32(float x) {
    uint32_t y; asm("cvt.rna.tf32.f32 %0, %1;" : "=r"(y) : "f"(x)); return y;
}
__device__ __forceinline__ void mma_tf32(float* d, const uint32_t* a, const uint32_t* b) {
    asm volatile("mma.sync.aligned.m16n8k8.row.col.f32.tf32.tf32.f32 "
                 "{%0,%1,%2,%3}, {%4,%5,%6,%7}, {%8,%9}, {%0,%1,%2,%3};"
                 : "+f"(d[0]), "+f"(d[1]), "+f"(d[2]), "+f"(d[3])
                 : "r"(a[0]), "r"(a[1]), "r"(a[2]), "r"(a[3]), "r"(b[0]), "r"(b[1]));
}
__device__ __forceinline__ void cp16(float* dst, const float* src) {
    uint32_t d = (uint32_t)__cvta_generic_to_shared(dst);
    asm volatile("cp.async.cg.shared.global [%0], [%1], 16;" :: "r"(d), "l"(src));
}

__global__ __launch_bounds__(256, 1) void attn_kernel(
    const float* __restrict__ z,
    const float* __restrict__ gq, const float* __restrict__ gk,
    const float* __restrict__ gv, const float* __restrict__ gg,
    float* __restrict__ og) {

    extern __shared__ float smem[];
    float* Ksm = smem;
    float* Vsm = smem + 64 * K_STRIDE;
    float* Psm = Vsm + 64 * V_STRIDE;

    const int tid  = threadIdx.x;
    const int lane = tid & 31, warp = tid >> 5;
    const int h = warp >> 1, qh = warp & 1;
    const int gid = lane >> 2, ctg = lane & 3;
    const int qg0 = blockIdx.x * 32;

    // colsum_h = sum_c lnz[c]*Wbias[c][h]   (constants -> identical per thread)
    float csum0 = 0.f, csum1 = 0.f, csum2 = 0.f, csum3 = 0.f;
    #pragma unroll
    for (int c = 0; c < CZ; c++) {
        float l = c_lnz[c];
        csum0 += l * c_wb[c*4+0]; csum1 += l * c_wb[c*4+1];
        csum2 += l * c_wb[c*4+2]; csum3 += l * c_wb[c*4+3];
    }

    // Q fragments (A of m16n8k8 tf32), q is pre-scaled by 1/sqrt(c)
    uint32_t qa[4][4];
    {
        int r0 = qg0 + qh * 16 + gid;
        const float* qp = gq + (size_t)r0 * CDIM + h * HDIM + ctg;
        #pragma unroll
        for (int ks = 0; ks < 4; ks++) {
            qa[ks][0] = f2tf32(qp[ks*8]);
            qa[ks][1] = f2tf32(qp[8*CDIM + ks*8]);
            qa[ks][2] = f2tf32(qp[ks*8 + 4]);
            qa[ks][3] = f2tf32(qp[8*CDIM + ks*8 + 4]);
        }
    }

    float O[4][4];
    #pragma unroll
    for (int i = 0; i < 4; i++) { O[i][0]=O[i][1]=O[i][2]=O[i][3]=0.f; }
    float m1 = -1e30f, m2 = -1e30f, l1 = 0.f, l2 = 0.f;

    const int kk0 = tid & 63;   // key within tile for bias phase
    const int qq0 = tid >> 6;   // base q row (0..3) for bias phase

    for (int kb = 0; kb < NSEQ; kb += 64) {
        __syncthreads();   // previous tile fully consumed

        // ---- prefetch K/V tile into smem (cp.async; overlaps with z stream)
        #pragma unroll
        for (int i = 0; i < 8; i++) {
            int e = tid + i * 256;
            int r = e >> 5, c4 = e & 31;
            cp16(Ksm + r * K_STRIDE + c4 * 4, gk + (size_t)(kb + r) * CDIM + c4 * 4);
        }
        #pragma unroll
        for (int i = 0; i < 8; i++) {
            int e = tid + i * 256;
            int r = e >> 5, c4 = e & 31;
            cp16(Vsm + r * V_STRIDE + c4 * 4, gv + (size_t)(kb + r) * CDIM + c4 * 4);
        }
        asm volatile("cp.async.commit_group;" ::: "memory");

        // ---- bias phase: LN(z)@Wbias fused, 8 (q,k) pairs per thread
        {
            float4 zb0, zb1, zb2, zb3;
            {
                const float4* zp = (const float4*)(z + ((size_t)(qg0 + qq0) * NSEQ + kb + kk0) * CZ);
                zb0 = zp[0]; zb1 = zp[1]; zb2 = zp[2]; zb3 = zp[3];
            }
            #pragma unroll
            for (int qi = 0; qi < 8; qi++) {
                float4 zc[4] = { zb0, zb1, zb2, zb3 };
                if (qi < 7) {
                    const float4* zn = (const float4*)(z + ((size_t)(qg0 + qq0 + (qi+1)*4) * NSEQ + kb + kk0) * CZ);
                    zb0 = zn[0]; zb1 = zn[1]; zb2 = zn[2]; zb3 = zn[3];
                }
                float s1 = 0.f, s2 = 0.f, d0 = 0.f, d1 = 0.f, d2 = 0.f, d3 = 0.f;
                #pragma unroll
                for (int j = 0; j < 4; j++) {
                    float4 v = zc[j];
                    int cb = j * 4;
                    s1 += v.x + v.y + v.z + v.w;
                    s2 += v.x*v.x + v.y*v.y + v.z*v.z + v.w*v.w;
                    float zl;
                    zl = v.x * c_lnz[cb+0];
                    d0 += zl*c_wb[(cb+0)*4+0]; d1 += zl*c_wb[(cb+0)*4+1];
                    d2 += zl*c_wb[(cb+0)*4+2]; d3 += zl*c_wb[(cb+0)*4+3];
                    zl = v.y * c_lnz[cb+1];
                    d0 += zl*c_wb[(cb+1)*4+0]; d1 += zl*c_wb[(cb+1)*4+1];
                    d2 += zl*c_wb[(cb+1)*4+2]; d3 += zl*c_wb[(cb+1)*4+3];
                    zl = v.z * c_lnz[cb+2];
                    d0 += zl*c_wb[(cb+2)*4+0]; d1 += zl*c_wb[(cb+2)*4+1];
                    d2 += zl*c_wb[(cb+2)*4+2]; d3 += zl*c_wb[(cb+2)*4+3];
                    zl = v.w * c_lnz[cb+3];
                    d0 += zl*c_wb[(cb+3)*4+0]; d1 += zl*c_wb[(cb+3)*4+1];
                    d2 += zl*c_wb[(cb+3)*4+2]; d3 += zl*c_wb[(cb+3)*4+3];
                }
                float mm = s1 * (1.f/CZ);
                float var = s2 * (1.f/CZ) - mm * mm;
                float rstd = rsqrtf(var + EPS);
                int q = qq0 + qi * 4;
                float* pb = Psm + q * P_STRIDE + kk0;
                pb[0 * 32 * P_STRIDE] = (d0 - mm * csum0) * rstd;
                pb[1 * 32 * P_STRIDE] = (d1 - mm * csum1) * rstd;
                pb[2 * 32 * P_STRIDE] = (d2 - mm * csum2) * rstd;
                pb[3 * 32 * P_STRIDE] = (d3 - mm * csum3) * rstd;
            }
        }
        asm volatile("cp.async.wait_group 0;" ::: "memory");
        __syncthreads();   // bias + K/V visible to everyone

        // ---- QK^T (tf32 mma): S[16q x 64k] per warp
        float S[8][4];
        #pragma unroll
        for (int nt = 0; nt < 8; nt++) {
            S[nt][0] = S[nt][1] = S[nt][2] = S[nt][3] = 0.f;
            const float* kp = Ksm + (nt * 8 + gid) * K_STRIDE + h * HDIM + ctg;
            #pragma unroll
            for (int ks = 0; ks < 4; ks++) {
                uint32_t b[2];
                b[0] = __float_as_uint(kp[ks * 8]);
                b[1] = __float_as_uint(kp[ks * 8 + 4]);
                mma_tf32(S[nt], qa[ks], b);
            }
        }

        // ---- bias add + online softmax
        float* pwarp = Psm + h * 32 * P_STRIDE + (qh * 16) * P_STRIDE;
        float mx1 = -1e30f, mx2 = -1e30f;
        #pragma unroll
        for (int nt = 0; nt < 8; nt++) {
            int col = nt * 8 + 2 * ctg;
            S[nt][0] += pwarp[gid * P_STRIDE + col];
            S[nt][1] += pwarp[gid * P_STRIDE + col + 1];
            S[nt][2] += pwarp[(gid + 8) * P_STRIDE + col];
            S[nt][3] += pwarp[(gid + 8) * P_STRIDE + col + 1];
            mx1 = fmaxf(mx1, fmaxf(S[nt][0], S[nt][1]));
            mx2 = fmaxf(mx2, fmaxf(S[nt][2], S[nt][3]));
        }
        mx1 = fmaxf(mx1, __shfl_xor_sync(~0u, mx1, 1));
        mx1 = fmaxf(mx1, __shfl_xor_sync(~0u, mx1, 2));
        mx2 = fmaxf(mx2, __shfl_xor_sync(~0u, mx2, 1));
        mx2 = fmaxf(mx2, __shfl_xor_sync(~0u, mx2, 2));
        float mn1 = fmaxf(m1, mx1), mn2 = fmaxf(m2, mx2);
        float al1 = __expf(m1 - mn1), al2 = __expf(m2 - mn2);
        float rs1 = 0.f, rs2 = 0.f;
        #pragma unroll
        for (int nt = 0; nt < 8; nt++) {
            float p0 = __expf(S[nt][0] - mn1);
            float p1 = __expf(S[nt][1] - mn1);
            float p2 = __expf(S[nt][2] - mn2);
            float p3 = __expf(S[nt][3] - mn2);
            rs1 += p0 + p1; rs2 += p2 + p3;
            int col = nt * 8 + 2 * ctg;
            pwarp[gid * P_STRIDE + col]           = __uint_as_float(f2tf32(p0));
            pwarp[gid * P_STRIDE + col + 1]       = __uint_as_float(f2tf32(p1));
            pwarp[(gid + 8) * P_STRIDE + col]     = __uint_as_float(f2tf32(p2));
            pwarp[(gid + 8) * P_STRIDE + col + 1] = __uint_as_float(f2tf32(p3));
        }
        rs1 += __shfl_xor_sync(~0u, rs1, 1); rs1 += __shfl_xor_sync(~0u, rs1, 2);
        rs2 += __shfl_xor_sync(~0u, rs2, 1); rs2 += __shfl_xor_sync(~0u, rs2, 2);
        l1 = l1 * al1 + rs1; l2 = l2 * al2 + rs2;
        m1 = mn1; m2 = mn2;
        #pragma unroll
        for (int on = 0; on < 4; on++) {
            O[on][0] *= al1; O[on][1] *= al1; O[on][2] *= al2; O[on][3] *= al2;
        }
        __syncwarp();

        // ---- PV (tf32 mma): O[16q x 32c] += P[16q x 64k] @ V[64k x 32c]
        #pragma unroll
        for (int on = 0; on < 4; on++) {
            #pragma unroll
            for (int ks = 0; ks < 8; ks++) {
                uint32_t a[4], b[2];
                const float* pp = pwarp + gid * P_STRIDE + ks * 8 + ctg;
                a[0] = __float_as_uint(pp[0]);
                a[1] = __float_as_uint(pp[8 * P_STRIDE]);
                a[2] = __float_as_uint(pp[4]);
                a[3] = __float_as_uint(pp[8 * P_STRIDE + 4]);
                const float* vp = Vsm + (ks * 8 + ctg) * V_STRIDE + h * HDIM + on * 8 + gid;
                b[0] = __float_as_uint(vp[0]);
                b[1] = __float_as_uint(vp[4 * V_STRIDE]);
                mma_tf32(O[on], a, b);
            }
        }
    }

    // ---- epilogue: normalize, gate, store
    float r1 = 1.f / l1, r2 = 1.f / l2;
    int row1 = qg0 + qh * 16 + gid, row2 = row1 + 8;
    #pragma unroll
    for (int on = 0; on < 4; on++) {
        int col = h * HDIM + on * 8 + 2 * ctg;
        size_t i1 = (size_t)row1 * CDIM + col;
        size_t i2 = (size_t)row2 * CDIM + col;
        og[i1]     = O[on][0] * r1 * gg[i1];
        og[i1 + 1] = O[on][1] * r1 * gg[i1 + 1];
        og[i2]     = O[on][2] * r2 * gg[i2];
        og[i2 + 1] = O[on][3] * r2 * gg[i2 + 1];
    }
}

// ------------------------------ launch -------------------------------------
extern "C" void kernel_launch(void* const* d_in, const int* in_sizes, int n_in,
                              void* d_out, int out_size) {
    const float* a_q      = (const float*)d_in[0];
    const float* a_k      = (const float*)d_in[1];
    const float* z        = (const float*)d_in[2];
    const float* s_q      = (const float*)d_in[3];
    const float* s_k      = (const float*)d_in[4];
    const float* Wg_q     = (const float*)d_in[5];
    const float* bg_q     = (const float*)d_in[6];
    const float* Wb_q     = (const float*)d_in[7];
    const float* sscale_q = (const float*)d_in[8];
    const float* Wg_k     = (const float*)d_in[9];
    const float* bg_k     = (const float*)d_in[10];
    const float* Wb_k     = (const float*)d_in[11];
    const float* sscale_k = (const float*)d_in[12];
    const float* lnz      = (const float*)d_in[13];
    const float* Wq       = (const float*)d_in[14];
    const float* bq       = (const float*)d_in[15];
    const float* Wk       = (const float*)d_in[16];
    const float* Wv       = (const float*)d_in[17];
    const float* Wbias    = (const float*)d_in[18];
    const float* Wgate    = (const float*)d_in[19];
    const float* Wo       = (const float*)d_in[20];
    const float* Ws       = (const float*)d_in[21];
    const float* bs       = (const float*)d_in[22];

    float* scratch = nullptr;
    cudaGetSymbolAddress((void**)&scratch, g_scratch);
    const size_t SL = (size_t)NSEQ * CDIM;
    float* lnA_q = scratch + 0 * SL;
    float* sn_q  = scratch + 1 * SL;
    float* lnA_k = scratch + 2 * SL;
    float* sn_k  = scratch + 3 * SL;
    float* aq    = scratch + 4 * SL;
    float* ak    = scratch + 5 * SL;
    float* qbuf  = scratch + 6 * SL;
    float* gbuf  = scratch + 7 * SL;
    float* kbuf  = scratch + 8 * SL;
    float* vbuf  = scratch + 9 * SL;
    float* ogbuf = scratch + 10 * SL;

    cudaMemcpyToSymbolAsync(c_wb, Wbias, CZ * NHEAD * sizeof(float), 0,
                            cudaMemcpyDeviceToDevice, 0);
    cudaMemcpyToSymbolAsync(c_lnz, lnz, CZ * sizeof(float), 0,
                            cudaMemcpyDeviceToDevice, 0);

    ln_kernel<<<NSEQ / 8, 256>>>(a_q, s_q, sscale_q, lnA_q, sn_q);
    ln_kernel<<<NSEQ / 8, 256>>>(a_k, s_k, sscale_k, lnA_k, sn_k);

    dual_gemm<MODE_ADALN><<<NSEQ / 32, 256>>>(sn_q, sn_q, Wg_q, Wb_q, bg_q, nullptr,
                                              lnA_q, aq, nullptr);
    dual_gemm<MODE_ADALN><<<NSEQ / 32, 256>>>(sn_k, sn_k, Wg_k, Wb_k, bg_k, nullptr,
                                              lnA_k, ak, nullptr);
    dual_gemm<MODE_QG><<<NSEQ / 32, 256>>>(aq, aq, Wq, Wgate, bq, nullptr,
                                           nullptr, qbuf, gbuf);
    dual_gemm<MODE_KV><<<NSEQ / 32, 256>>>(ak, ak, Wk, Wv, nullptr, nullptr,
                                           nullptr, kbuf, vbuf);

    cudaFuncSetAttribute(attn_kernel, cudaFuncAttributeMaxDynamicSharedMemorySize,
                         SMEM_BYTES);
    attn_kernel<<<NSEQ / 32, 256, SMEM_BYTES>>>(z, qbuf, kbuf, vbuf, gbuf, ogbuf);

    dual_gemm<MODE_FINAL><<<NSEQ / 32, 256>>>(ogbuf, s_q, Wo, Ws, nullptr, bs,
                                              nullptr, (float*)d_out, nullptr);
}